// round 10
// baseline (speedup 1.0000x reference)
#include <cuda_runtime.h>

// SpectralConv2d via truncated-mode DFTs, fp32 SIMT, packed f32x2 FMA (FFMA2).

#define BB 16
#define CC 64
#define HH 256
#define WW 256
#define M1 20
#define M2 20
#define QQ 40   // q<20 -> ky=236+q (w2, m=q); q>=20 -> ky=q-20 (w1, m=q-20); freq f = q-20

typedef unsigned long long u64;

__device__ __forceinline__ u64 pk2(float lo, float hi) {
    u64 r; asm("mov.b64 %0,{%1,%2};" : "=l"(r) : "f"(lo), "f"(hi)); return r;
}
__device__ __forceinline__ void upk2(u64 v, float& lo, float& hi) {
    asm("mov.b64 {%0,%1},%2;" : "=f"(lo), "=f"(hi) : "l"(v));
}
__device__ __forceinline__ u64 fma2(u64 a, u64 b, u64 c) {
    u64 d; asm("fma.rn.f32x2 %0,%1,%2,%3;" : "=l"(d) : "l"(a), "l"(b), "l"(c)); return d;
}
__device__ __forceinline__ u64 mul2(u64 a, u64 b) {
    u64 d; asm("mul.rn.f32x2 %0,%1,%2;" : "=l"(d) : "l"(a), "l"(b)); return d;
}

__device__ float2 g_Y1[BB*CC*HH*M2];   // after W-DFT   [b,c,h,k2]
__device__ float2 g_Zq[BB*CC*QQ*M2];   // after H-DFT   [b,c,q,k2]
__device__ float2 g_Zo[BB*CC*QQ*M2];   // after mixing  [b,o,q,k2]

// ---------------------------------------------------------------------------
// Stage A: Y1[row,k] = sum_w x[row,w] e^{-2pi i k w/256}, k=0..19.
// Folded real input: u=x[w]+x[256-w], v=x[w]-x[256-w], + x0/x128 edge.
// Planes sfu/sfv[wl][row] -> row-pairs are LDS.64. Packed broadcast twiddles.
// Block: 256 rows, 256 threads; thread -> (4 rows, 5 k) = (2 row-pairs, 5 k).
// ---------------------------------------------------------------------------
#define RA 256
#define WCH 32
__global__ void __launch_bounds__(256, 2) kA(const float* __restrict__ x) {
    __shared__ float2 tw[256];            // 2KB
    __shared__ float sfu[WCH][RA + 2];    // 33KB
    __shared__ float sfv[WCH][RA + 2];    // 33KB
    __shared__ u64 twc2[WCH][M2];         // 5KB  (c,c)
    __shared__ u64 tws2[WCH][M2];         // 5KB  (s,s)
    int tid = threadIdx.x;
    {
        float s, c;
        sincospif((float)tid * (1.0f / 128.0f), &s, &c);
        tw[tid] = make_float2(c, s);
    }
    int row0 = blockIdx.x * RA;
    int rg = tid >> 2;             // rows 4rg..4rg+3
    int k0 = (tid & 3) * 5;

    u64 ar2[2][5], ai2[2][5];
    #pragma unroll
    for (int p = 0; p < 2; ++p)
        #pragma unroll
        for (int j = 0; j < 5; ++j) { ar2[p][j] = 0ULL; ai2[p][j] = 0ULL; }
    float ex[4], e128[4];
    #pragma unroll
    for (int u = 0; u < 4; ++u) { ex[u] = 0.f; e128[u] = 0.f; }

    for (int wc = 0; wc < 128; wc += WCH) {
        __syncthreads();
        for (int t = tid; t < RA * WCH; t += 256) {
            int r = t >> 5, wl = t & 31;
            int w = wc + wl;
            const float* xr = x + (size_t)(row0 + r) * WW;
            if (w == 0) {
                sfu[0][r] = xr[0];
                sfv[0][r] = xr[128];
            } else {
                float a = xr[w];
                float b = xr[256 - w];
                sfu[wl][r] = a + b;
                sfv[wl][r] = a - b;
            }
        }
        for (int t = tid; t < WCH * M2; t += 256) {
            int wl = t / M2, k = t - wl * M2;
            float2 cs = tw[((wc + wl) * k) & 255];
            twc2[wl][k] = pk2(cs.x, cs.x);
            tws2[wl][k] = pk2(cs.y, cs.y);
        }
        __syncthreads();

        int wl0 = 0;
        if (wc == 0) {
            #pragma unroll
            for (int u = 0; u < 4; ++u) {
                ex[u]   = sfu[0][4 * rg + u];
                e128[u] = sfv[0][4 * rg + u];
            }
            wl0 = 1;
        }

        #pragma unroll 2
        for (int wl = wl0; wl < WCH; ++wl) {
            u64 uxA = *(const u64*)&sfu[wl][4 * rg];
            u64 uxB = *(const u64*)&sfu[wl][4 * rg + 2];
            u64 vxA = *(const u64*)&sfv[wl][4 * rg];
            u64 vxB = *(const u64*)&sfv[wl][4 * rg + 2];
            #pragma unroll
            for (int j = 0; j < 5; ++j) {
                u64 c2 = twc2[wl][k0 + j];
                u64 s2 = tws2[wl][k0 + j];
                ar2[0][j] = fma2(uxA, c2, ar2[0][j]);
                ar2[1][j] = fma2(uxB, c2, ar2[1][j]);
                ai2[0][j] = fma2(vxA, s2, ai2[0][j]);
                ai2[1][j] = fma2(vxB, s2, ai2[1][j]);
            }
        }
    }

    #pragma unroll
    for (int p = 0; p < 2; ++p) {
        float2* yo0 = g_Y1 + (size_t)(row0 + 4 * rg + 2 * p) * M2;
        float2* yo1 = yo0 + M2;
        #pragma unroll
        for (int j = 0; j < 5; ++j) {
            int k = k0 + j;
            float a0, a1, b0, b1;
            upk2(ar2[p][j], a0, a1);
            upk2(ai2[p][j], b0, b1);
            float sgn = (k & 1) ? -1.f : 1.f;
            yo0[k] = make_float2(a0 + ex[2 * p]     + sgn * e128[2 * p],     -b0);
            yo1[k] = make_float2(a1 + ex[2 * p + 1] + sgn * e128[2 * p + 1], -b1);
        }
    }
}

// ---------------------------------------------------------------------------
// Stage B: Zq[bc,q,k2] = sum_h Y1[bc,h,k2] e^{-2pi i f h/256}, f=q-20.
// h<->h+128 parity fold; x/y planes so k2-pairs are LDS.64; packed twiddles.
// Block per bc; thread -> (q, 4 k2).
// ---------------------------------------------------------------------------
__global__ void __launch_bounds__(256) kB() {
    __shared__ float sYpx[128][M2], sYpy[128][M2];  // 20KB
    __shared__ float sYmx[128][M2], sYmy[128][M2];  // 20KB
    __shared__ u64 t2c[256], t2s[256], t2sn[256];   // 6KB
    int tid = threadIdx.x;
    {
        float s, c;
        sincospif((float)tid * (1.0f / 128.0f), &s, &c);
        t2c[tid]  = pk2(c, c);
        t2s[tid]  = pk2(s, s);
        t2sn[tid] = pk2(-s, -s);
    }
    int bc = blockIdx.x;
    const float2* ysrc = g_Y1 + (size_t)bc * HH * M2;
    for (int t = tid; t < 128 * M2; t += 256) {
        int h = t / M2, k = t - h * M2;
        float2 a = ysrc[t];
        float2 b = ysrc[t + 128 * M2];
        sYpx[h][k] = a.x + b.x;
        sYpy[h][k] = a.y + b.y;
        sYmx[h][k] = a.x - b.x;
        sYmy[h][k] = a.y - b.y;
    }
    __syncthreads();

    if (tid < 200) {
        int q = tid / 5;
        int k0 = (tid % 5) * 4;
        int f = q - M1;
        const float (*Yx)[M2] = (f & 1) ? sYmx : sYpx;
        const float (*Yy)[M2] = (f & 1) ? sYmy : sYpy;
        u64 arA = 0, arB = 0, aiA = 0, aiB = 0;
        int idx = 0, step = f & 255;
        #pragma unroll 4
        for (int h = 0; h < 128; ++h) {
            u64 c2 = t2c[idx], s2 = t2s[idx], sn2 = t2sn[idx];
            u64 xA = *(const u64*)&Yx[h][k0];
            u64 xB = *(const u64*)&Yx[h][k0 + 2];
            u64 yA = *(const u64*)&Yy[h][k0];
            u64 yB = *(const u64*)&Yy[h][k0 + 2];
            arA = fma2(xA, c2, arA); arA = fma2(yA, s2, arA);
            aiA = fma2(yA, c2, aiA); aiA = fma2(xA, sn2, aiA);
            arB = fma2(xB, c2, arB); arB = fma2(yB, s2, arB);
            aiB = fma2(yB, c2, aiB); aiB = fma2(xB, sn2, aiB);
            idx = (idx + step) & 255;
        }
        float2* zo = g_Zq + (size_t)bc * QQ * M2 + q * M2 + k0;
        float r0, r1, r2, r3, i0, i1, i2, i3;
        upk2(arA, r0, r1); upk2(arB, r2, r3);
        upk2(aiA, i0, i1); upk2(aiB, i2, i3);
        zo[0] = make_float2(r0, i0);
        zo[1] = make_float2(r1, i1);
        zo[2] = make_float2(r2, i2);
        zo[3] = make_float2(r3, i3);
    }
}

// ---------------------------------------------------------------------------
// Stage C: Zo[b,o,q,k2] = sum_i Zq[b,i,q,k2] * Wsel[i,o,m,k2]  (complex)
// Block per (q, k2-quad); Z planes x / y / -y; weights as ulonglong2 (pairs).
// thread -> (o, 4 b, 4 k2 = 2 k2-pairs).
// ---------------------------------------------------------------------------
__global__ void __launch_bounds__(256) kC(const float* __restrict__ w1r, const float* __restrict__ w1i,
                                          const float* __restrict__ w2r, const float* __restrict__ w2i) {
    __shared__ float sZx[BB][CC][4];   // 16KB
    __shared__ float sZy[BB][CC][4];   // 16KB
    __shared__ float sZyn[BB][CC][4];  // 16KB
    int tid = threadIdx.x;
    int q = blockIdx.x / 5, k2b = (blockIdx.x % 5) * 4;

    for (int t = tid; t < BB * CC; t += 256) {
        const float2* zsrc = g_Zq + (size_t)t * (QQ * M2) + q * M2 + k2b;
        float4 v0 = *(const float4*)&zsrc[0];   // x0 y0 x1 y1
        float4 v1 = *(const float4*)&zsrc[2];   // x2 y2 x3 y3
        int b = t >> 6, i = t & 63;
        sZx[b][i][0] = v0.x; sZx[b][i][1] = v0.z; sZx[b][i][2] = v1.x; sZx[b][i][3] = v1.z;
        sZy[b][i][0] = v0.y; sZy[b][i][1] = v0.w; sZy[b][i][2] = v1.y; sZy[b][i][3] = v1.w;
        sZyn[b][i][0] = -v0.y; sZyn[b][i][1] = -v0.w; sZyn[b][i][2] = -v1.y; sZyn[b][i][3] = -v1.w;
    }

    const float *wr, *wi;
    int m;
    if (q < M1) { wr = w2r; wi = w2i; m = q; }
    else        { wr = w1r; wi = w1i; m = q - M1; }
    __syncthreads();

    int o = tid & 63;
    int bq = tid >> 6;   // b = bq + 4j
    u64 ar2[4][2], ai2[4][2];
    #pragma unroll
    for (int j = 0; j < 4; ++j) { ar2[j][0] = ar2[j][1] = 0; ai2[j][0] = ai2[j][1] = 0; }

    size_t wbase = (size_t)o * (M1 * M2) + m * M2 + k2b;
    #pragma unroll 2
    for (int i = 0; i < CC; ++i) {
        ulonglong2 wr2 = *(const ulonglong2*)&wr[wbase + (size_t)i * (CC * M1 * M2)];
        ulonglong2 wi2 = *(const ulonglong2*)&wi[wbase + (size_t)i * (CC * M1 * M2)];
        #pragma unroll
        for (int j = 0; j < 4; ++j) {
            int b = bq + 4 * j;
            ulonglong2 zx  = *(const ulonglong2*)&sZx[b][i][0];
            ulonglong2 zy  = *(const ulonglong2*)&sZy[b][i][0];
            ulonglong2 zyn = *(const ulonglong2*)&sZyn[b][i][0];
            ar2[j][0] = fma2(zx.x,  wr2.x, ar2[j][0]);
            ar2[j][0] = fma2(zyn.x, wi2.x, ar2[j][0]);
            ar2[j][1] = fma2(zx.y,  wr2.y, ar2[j][1]);
            ar2[j][1] = fma2(zyn.y, wi2.y, ar2[j][1]);
            ai2[j][0] = fma2(zx.x,  wi2.x, ai2[j][0]);
            ai2[j][0] = fma2(zy.x,  wr2.x, ai2[j][0]);
            ai2[j][1] = fma2(zx.y,  wi2.y, ai2[j][1]);
            ai2[j][1] = fma2(zy.y,  wr2.y, ai2[j][1]);
        }
    }
    #pragma unroll
    for (int j = 0; j < 4; ++j) {
        int b = bq + 4 * j;
        float2* zo = g_Zo + (((size_t)(b * CC + o)) * QQ + q) * M2 + k2b;
        float r0, r1, r2, r3, i0, i1, i2, i3;
        upk2(ar2[j][0], r0, r1); upk2(ar2[j][1], r2, r3);
        upk2(ai2[j][0], i0, i1); upk2(ai2[j][1], i2, i3);
        *(float4*)&zo[0] = make_float4(r0, i0, r1, i1);
        *(float4*)&zo[2] = make_float4(r2, i2, r3, i3);
    }
}

// ---------------------------------------------------------------------------
// Stage D (fused): block = one bo (grid 1024).
// phase1: G[h,k] = sum_q Zo[q,k] e^{+2pi i (q-20)h/256}, h<->h+128 fold via
//         q-parity; Z planes, packed k-pairs -> 20 FFMA2/q. Transposed store.
// phase2: h-pair x 4w packed tile; broadcast-packed twiddle tables sC2/sS2.
// ---------------------------------------------------------------------------
__global__ void __launch_bounds__(256) kD(float* __restrict__ out) {
    __shared__ float2 tw[256];           // 2KB
    __shared__ float sZx[QQ][M2];        // 3.2KB
    __shared__ float sZy[QQ][M2];        // 3.2KB
    __shared__ u64 t2c[256], t2s[256], t2sn[256];  // 6KB
    __shared__ float sGx[M2][HH];        // 20KB
    __shared__ float sGy[M2 - 1][HH];    // 19KB
    __shared__ u64 sC2[M2][128];         // 20KB  (c,c)
    __shared__ u64 sS2[M2][128];         // 20KB  (s,s)
    int tid = threadIdx.x;
    {
        float s, c;
        sincospif((float)tid * (1.0f / 128.0f), &s, &c);
        tw[tid] = make_float2(c, s);
        t2c[tid]  = pk2(c, c);
        t2s[tid]  = pk2(s, s);
        t2sn[tid] = pk2(-s, -s);
    }
    int bo = blockIdx.x;

    {
        const float2* zsrc = g_Zo + (size_t)bo * QQ * M2;
        for (int t = tid; t < QQ * M2; t += 256) {
            float2 z = zsrc[t];
            int q = t / M2, k = t - q * M2;
            sZx[q][k] = z.x;
            sZy[q][k] = z.y;
        }
    }
    __syncthreads();

    for (int t = tid; t < M2 * 128; t += 256) {
        int k = t >> 7, wp = t & 127;
        float2 cs = tw[(k * wp) & 255];
        sC2[k][wp] = pk2(cs.x, cs.x);
        sS2[k][wp] = pk2(cs.y, cs.y);
    }

    // ---- phase 1 ----
    {
        int h = tid & 127;
        int k0 = (tid >> 7) * 10;     // 0 or 10
        u64 ger2[5], gei2[5], gor2[5], goi2[5];
        #pragma unroll
        for (int p = 0; p < 5; ++p) { ger2[p] = gei2[p] = gor2[p] = goi2[p] = 0; }

        int step = (2 * h) & 255;
        int idx = (-20 * h) & 255;
        #pragma unroll 2
        for (int qq = 0; qq < 20; ++qq) {
            u64 c2 = t2c[idx], s2 = t2s[idx], sn2 = t2sn[idx];
            #pragma unroll
            for (int p = 0; p < 5; ++p) {
                u64 zx2 = *(const u64*)&sZx[2 * qq][k0 + 2 * p];
                u64 zy2 = *(const u64*)&sZy[2 * qq][k0 + 2 * p];
                ger2[p] = fma2(zx2, c2, ger2[p]);  ger2[p] = fma2(zy2, sn2, ger2[p]);
                gei2[p] = fma2(zx2, s2, gei2[p]);  gei2[p] = fma2(zy2, c2, gei2[p]);
            }
            idx = (idx + step) & 255;
        }
        idx = (-19 * h) & 255;
        #pragma unroll 2
        for (int qq = 0; qq < 20; ++qq) {
            u64 c2 = t2c[idx], s2 = t2s[idx], sn2 = t2sn[idx];
            #pragma unroll
            for (int p = 0; p < 5; ++p) {
                u64 zx2 = *(const u64*)&sZx[2 * qq + 1][k0 + 2 * p];
                u64 zy2 = *(const u64*)&sZy[2 * qq + 1][k0 + 2 * p];
                gor2[p] = fma2(zx2, c2, gor2[p]);  gor2[p] = fma2(zy2, sn2, gor2[p]);
                goi2[p] = fma2(zx2, s2, goi2[p]);  goi2[p] = fma2(zy2, c2, goi2[p]);
            }
            idx = (idx + step) & 255;
        }
        #pragma unroll
        for (int p = 0; p < 5; ++p) {
            float e0, e1, f0, f1, o0, o1, p0, p1;
            upk2(ger2[p], e0, e1);
            upk2(gor2[p], o0, o1);
            upk2(gei2[p], f0, f1);
            upk2(goi2[p], p0, p1);
            int k = k0 + 2 * p;
            sGx[k][h]           = e0 + o0;
            sGx[k][h + 128]     = e0 - o0;
            sGx[k + 1][h]       = e1 + o1;
            sGx[k + 1][h + 128] = e1 - o1;
            if (k > 0) {
                sGy[k - 1][h]       = f0 + p0;
                sGy[k - 1][h + 128] = f0 - p0;
            }
            sGy[k][h]       = f1 + p1;
            sGy[k][h + 128] = f1 - p1;
        }
    }
    __syncthreads();

    // ---- phase 2: (2 h-pairs) x 4w packed tiles ----
    int wg = tid & 31;        // wp0 = 4*wg
    int hgb = tid >> 5;       // 0..7
    int wp0 = wg * 4;
    const float sc = 2.0f / 65536.0f;
    const u64 half2 = pk2(0.5f, 0.5f);

    #pragma unroll 1
    for (int it = 0; it < 8; ++it) {
        int h0 = it * 32 + hgb * 4;
        u64 C2[2][4], S2[2][4];
        {
            ulonglong2 g0 = *(const ulonglong2*)&sGx[0][h0];
            u64 c0 = mul2(g0.x, half2);
            u64 c1 = mul2(g0.y, half2);
            #pragma unroll
            for (int b = 0; b < 4; ++b) {
                C2[0][b] = c0; C2[1][b] = c1;
                S2[0][b] = 0;  S2[1][b] = 0;
            }
        }
        #pragma unroll
        for (int k = 1; k < M2; ++k) {
            ulonglong2 gx = *(const ulonglong2*)&sGx[k][h0];
            ulonglong2 gy = *(const ulonglong2*)&sGy[k - 1][h0];
            ulonglong2 cA = *(const ulonglong2*)&sC2[k][wp0];
            ulonglong2 cB = *(const ulonglong2*)&sC2[k][wp0 + 2];
            ulonglong2 sA = *(const ulonglong2*)&sS2[k][wp0];
            ulonglong2 sB = *(const ulonglong2*)&sS2[k][wp0 + 2];
            C2[0][0] = fma2(gx.x, cA.x, C2[0][0]);
            C2[0][1] = fma2(gx.x, cA.y, C2[0][1]);
            C2[0][2] = fma2(gx.x, cB.x, C2[0][2]);
            C2[0][3] = fma2(gx.x, cB.y, C2[0][3]);
            C2[1][0] = fma2(gx.y, cA.x, C2[1][0]);
            C2[1][1] = fma2(gx.y, cA.y, C2[1][1]);
            C2[1][2] = fma2(gx.y, cB.x, C2[1][2]);
            C2[1][3] = fma2(gx.y, cB.y, C2[1][3]);
            S2[0][0] = fma2(gy.x, sA.x, S2[0][0]);
            S2[0][1] = fma2(gy.x, sA.y, S2[0][1]);
            S2[0][2] = fma2(gy.x, sB.x, S2[0][2]);
            S2[0][3] = fma2(gy.x, sB.y, S2[0][3]);
            S2[1][0] = fma2(gy.y, sA.x, S2[1][0]);
            S2[1][1] = fma2(gy.y, sA.y, S2[1][1]);
            S2[1][2] = fma2(gy.y, sB.x, S2[1][2]);
            S2[1][3] = fma2(gy.y, sB.y, S2[1][3]);
        }

        float Cv[4][4], Sv[4][4];
        #pragma unroll
        for (int p = 0; p < 2; ++p)
            #pragma unroll
            for (int b = 0; b < 4; ++b) {
                float lo, hi;
                upk2(C2[p][b], lo, hi);
                Cv[2 * p][b] = lo; Cv[2 * p + 1][b] = hi;
                upk2(S2[p][b], lo, hi);
                Sv[2 * p][b] = lo; Sv[2 * p + 1][b] = hi;
            }

        size_t rowbase = ((size_t)bo * HH + h0) * WW;
        #pragma unroll
        for (int a = 0; a < 4; ++a) {
            float4 fo;
            fo.x = (Cv[a][0] - Sv[a][0]) * sc;
            fo.y = (Cv[a][1] - Sv[a][1]) * sc;
            fo.z = (Cv[a][2] - Sv[a][2]) * sc;
            fo.w = (Cv[a][3] - Sv[a][3]) * sc;
            *(float4*)&out[rowbase + (size_t)a * WW + wp0] = fo;
            #pragma unroll
            for (int b = 0; b < 4; ++b) {
                int wp = wp0 + b;
                if (wp) out[rowbase + (size_t)a * WW + (256 - wp)] = (Cv[a][b] + Sv[a][b]) * sc;
            }
        }
    }

    // ---- w = 128 column ----
    {
        int h = tid;
        float acc = 0.5f * sGx[0][h];
        #pragma unroll
        for (int k = 1; k < M2; ++k)
            acc += (k & 1) ? -sGx[k][h] : sGx[k][h];
        out[((size_t)bo * HH + h) * WW + 128] = acc * sc;
    }
}

extern "C" void kernel_launch(void* const* d_in, const int* in_sizes, int n_in,
                              void* d_out, int out_size) {
    const float* x   = (const float*)d_in[0];
    const float* w1r = (const float*)d_in[1];
    const float* w1i = (const float*)d_in[2];
    const float* w2r = (const float*)d_in[3];
    const float* w2i = (const float*)d_in[4];
    float* out = (float*)d_out;

    kA<<<(BB * CC * HH) / RA, 256>>>(x);       // 1024 blocks
    kB<<<BB * CC, 256>>>();                     // 1024 blocks
    kC<<<QQ * 5, 256>>>(w1r, w1i, w2r, w2i);    // 200 blocks
    kD<<<BB * CC, 256>>>(out);                  // 1024 blocks
}

// round 11
// speedup vs baseline: 1.2609x; 1.2609x over previous
#include <cuda_runtime.h>

// SpectralConv2d via truncated-mode DFTs, fp32 SIMT, register-tiled.

#define BB 16
#define CC 64
#define HH 256
#define WW 256
#define M1 20
#define M2 20
#define QQ 40   // q<20 -> ky=236+q (w2, m=q); q>=20 -> ky=q-20 (w1, m=q-20); freq f = q-20

__device__ float2 g_Y1[BB*CC*HH*M2];   // after W-DFT   [b,c,h,k2]
__device__ float2 g_Zq[BB*CC*QQ*M2];   // after H-DFT   [b,c,q,k2]
__device__ float2 g_Zo[BB*CC*QQ*M2];   // after mixing  [b,o,q,k2]

// ---------------------------------------------------------------------------
// Stage A: Y1[row,k] = sum_w x[row,w] e^{-2pi i k w/256}, k=0..19.
// Folded real input. Block: 256 rows, 256 threads; thread -> (4 rows, 5 k).
// ---------------------------------------------------------------------------
#define RA 256
#define WCH 32
__global__ void __launch_bounds__(256, 2) kA(const float* __restrict__ x) {
    __shared__ float2 tw[256];
    __shared__ float2 sf[RA][WCH + 1];   // 67.6KB: (u,v); chunk0 [..][0] = (x0,x128)
    __shared__ float2 twa[WCH][M2];      // 5KB
    int tid = threadIdx.x;
    {
        float s, c;
        sincospif((float)tid * (1.0f / 128.0f), &s, &c);
        tw[tid] = make_float2(c, s);
    }
    int row0 = blockIdx.x * RA;
    int rg = tid >> 2;             // 0..63 -> rows 4rg..4rg+3
    int k0 = (tid & 3) * 5;

    float ar[4][5], ai[4][5];
    #pragma unroll
    for (int u = 0; u < 4; ++u)
        #pragma unroll
        for (int j = 0; j < 5; ++j) { ar[u][j] = 0.0f; ai[u][j] = 0.0f; }
    float2 e[4];
    #pragma unroll
    for (int u = 0; u < 4; ++u) e[u] = make_float2(0.f, 0.f);

    for (int wc = 0; wc < 128; wc += WCH) {
        __syncthreads();
        for (int t = tid; t < RA * WCH; t += 256) {
            int r = t >> 5, wl = t & 31;
            int w = wc + wl;
            const float* xr = x + (size_t)(row0 + r) * WW;
            float a = xr[w];
            if (w == 0) {
                sf[r][wl] = make_float2(a, xr[128]);
            } else {
                float b = xr[256 - w];
                sf[r][wl] = make_float2(a + b, a - b);
            }
        }
        for (int t = tid; t < WCH * M2; t += 256) {
            int wl = t / M2, k = t - wl * M2;
            twa[wl][k] = tw[((wc + wl) * k) & 255];
        }
        __syncthreads();

        int wl0 = 0;
        if (wc == 0) {
            #pragma unroll
            for (int u = 0; u < 4; ++u) e[u] = sf[4 * rg + u][0];
            wl0 = 1;
        }

        #pragma unroll 2
        for (int wl = wl0; wl < WCH; ++wl) {
            float2 uv[4];
            #pragma unroll
            for (int u = 0; u < 4; ++u) uv[u] = sf[4 * rg + u][wl];
            #pragma unroll
            for (int j = 0; j < 5; ++j) {
                float2 cs = twa[wl][k0 + j];
                #pragma unroll
                for (int u = 0; u < 4; ++u) {
                    ar[u][j] = fmaf(uv[u].x, cs.x, ar[u][j]);
                    ai[u][j] = fmaf(uv[u].y, cs.y, ai[u][j]);
                }
            }
        }
    }

    #pragma unroll
    for (int u = 0; u < 4; ++u) {
        float2* yo = g_Y1 + (size_t)(row0 + 4 * rg + u) * M2;
        #pragma unroll
        for (int j = 0; j < 5; ++j) {
            int k = k0 + j;
            float re = ar[u][j] + e[u].x + ((k & 1) ? -e[u].y : e[u].y);
            yo[k] = make_float2(re, -ai[u][j]);
        }
    }
}

// ---------------------------------------------------------------------------
// Stage B: Zq[bc,q,k2] = sum_h Y1[bc,h,k2] e^{-2pi i f h/256}, f=q-20.
// h<->h+128 parity fold. Block per bc; thread -> (q, 4 k2), LDS.128 Y loads.
// ---------------------------------------------------------------------------
__global__ void __launch_bounds__(256) kB() {
    __shared__ float2 tw[256];
    __shared__ float2 sYp[128][M2];  // 20KB
    __shared__ float2 sYm[128][M2];  // 20KB
    int tid = threadIdx.x;
    {
        float s, c;
        sincospif((float)tid * (1.0f / 128.0f), &s, &c);
        tw[tid] = make_float2(c, s);
    }
    int bc = blockIdx.x;
    const float2* ysrc = g_Y1 + (size_t)bc * HH * M2;
    for (int t = tid; t < 128 * M2; t += 256) {
        int h = t / M2, k = t - h * M2;
        float2 a = ysrc[t];
        float2 b = ysrc[t + 128 * M2];
        sYp[h][k] = make_float2(a.x + b.x, a.y + b.y);
        sYm[h][k] = make_float2(a.x - b.x, a.y - b.y);
    }
    __syncthreads();

    if (tid < 200) {
        int q = tid / 5;
        int k0 = (tid % 5) * 4;
        int f = q - M1;
        const float2 (*Ys)[M2] = (f & 1) ? sYm : sYp;
        float ar[4] = {0, 0, 0, 0}, ai[4] = {0, 0, 0, 0};
        int idx = 0, step = f & 255;
        #pragma unroll 4
        for (int h = 0; h < 128; ++h) {
            float2 cs = tw[idx];
            float4 yab = *(const float4*)&Ys[h][k0];
            float4 ycd = *(const float4*)&Ys[h][k0 + 2];
            float yx[4] = {yab.x, yab.z, ycd.x, ycd.z};
            float yy[4] = {yab.y, yab.w, ycd.y, ycd.w};
            #pragma unroll
            for (int j = 0; j < 4; ++j) {
                ar[j] = fmaf(yx[j], cs.x, fmaf(yy[j], cs.y, ar[j]));
                ai[j] = fmaf(yy[j], cs.x, fmaf(-yx[j], cs.y, ai[j]));
            }
            idx = (idx + step) & 255;
        }
        float2* zo = g_Zq + (size_t)bc * QQ * M2 + q * M2 + k0;
        #pragma unroll
        for (int j = 0; j < 4; ++j) zo[j] = make_float2(ar[j], ai[j]);
    }
}

// ---------------------------------------------------------------------------
// Stage C: Zo[b,o,q,k2] = sum_i Zq[b,i,q,k2] * Wsel[i,o,m,k2]  (complex)
// Block per (q, k2-quad); weights loaded as float4 across 4 k2 (LDG.128);
// thread -> (o, 4 b, 4 k2).
// ---------------------------------------------------------------------------
__global__ void __launch_bounds__(256) kC(const float* __restrict__ w1r, const float* __restrict__ w1i,
                                          const float* __restrict__ w2r, const float* __restrict__ w2i) {
    __shared__ float2 sZ[BB][CC][4];  // 32KB
    int tid = threadIdx.x;
    int q = blockIdx.x / 5, k2b = (blockIdx.x % 5) * 4;

    for (int t = tid; t < BB * CC * 2; t += 256) {
        int pair = t & 1;
        int ci = t >> 1;                 // b*64 + i
        float4 v = *(const float4*)&g_Zq[(size_t)ci * (QQ * M2) + q * M2 + k2b + pair * 2];
        *(float4*)&sZ[ci >> 6][ci & 63][pair * 2] = v;
    }

    const float *wr, *wi;
    int m;
    if (q < M1) { wr = w2r; wi = w2i; m = q; }
    else        { wr = w1r; wi = w1i; m = q - M1; }
    __syncthreads();

    int o = tid & 63;
    int bq = tid >> 6;   // b = bq + 4j
    float ar[4][4], ai[4][4];
    #pragma unroll
    for (int j = 0; j < 4; ++j)
        #pragma unroll
        for (int kk = 0; kk < 4; ++kk) { ar[j][kk] = 0.f; ai[j][kk] = 0.f; }

    size_t wbase = (size_t)o * (M1 * M2) + m * M2 + k2b;
    #pragma unroll 2
    for (int i = 0; i < CC; ++i) {
        float4 wr4 = *(const float4*)&wr[wbase + (size_t)i * (CC * M1 * M2)];
        float4 wi4 = *(const float4*)&wi[wbase + (size_t)i * (CC * M1 * M2)];
        float wra[4] = {wr4.x, wr4.y, wr4.z, wr4.w};
        float wia[4] = {wi4.x, wi4.y, wi4.z, wi4.w};
        #pragma unroll
        for (int j = 0; j < 4; ++j) {
            float4 za = *(const float4*)&sZ[bq + 4 * j][i][0];
            float4 zb = *(const float4*)&sZ[bq + 4 * j][i][2];
            float zx[4] = {za.x, za.z, zb.x, zb.z};
            float zy[4] = {za.y, za.w, zb.y, zb.w};
            #pragma unroll
            for (int kk = 0; kk < 4; ++kk) {
                ar[j][kk] = fmaf(zx[kk], wra[kk], fmaf(-zy[kk], wia[kk], ar[j][kk]));
                ai[j][kk] = fmaf(zx[kk], wia[kk], fmaf( zy[kk], wra[kk], ai[j][kk]));
            }
        }
    }
    #pragma unroll
    for (int j = 0; j < 4; ++j) {
        int b = bq + 4 * j;
        float2* zo = g_Zo + (((size_t)(b * CC + o)) * QQ + q) * M2 + k2b;
        float4 v0 = make_float4(ar[j][0], ai[j][0], ar[j][1], ai[j][1]);
        float4 v1 = make_float4(ar[j][2], ai[j][2], ar[j][3], ai[j][3]);
        *(float4*)&zo[0] = v0;
        *(float4*)&zo[2] = v1;
    }
}

// ---------------------------------------------------------------------------
// Stage D (fused): block = one bo (grid 1024).
// phase1: unchanged from the proven R9 version (h<->h+128 fold by q-parity).
// phase2: NEW wp<->128-wp parity fold. With Ce/Co/Se/So = even/odd-k partial
//   sums (A = g0/2 folded into Ce):
//     out[wp]      = Ce+Co-Se-So      out[256-wp] = Ce+Co+Se+So
//     out[128-wp]  = Ce-Co+Se-So      out[128+wp] = Ce-Co-Se+So
//   One twiddle set -> 4 columns: phase-2 FMAs halve. Tile 4h x 2wp (32 acc).
//   wp in 0..63; w = 64, 128, 192 handled in the per-h epilogue.
// ---------------------------------------------------------------------------
__global__ void __launch_bounds__(256) kD(float* __restrict__ out) {
    __shared__ float2 tw[256];          // 2KB
    __shared__ float2 sZ[QQ][M2];       // 6.25KB
    __shared__ float  sGx[M2][HH];      // 20KB
    __shared__ float  sGy[M2 - 1][HH];  // 19KB
    __shared__ float  sCw[M2][64];      // 5KB   cos(2pi k wp/256), wp<64
    __shared__ float  sSw[M2][64];      // 5KB   sin(2pi k wp/256), wp<64
    int tid = threadIdx.x;
    {
        float s, c;
        sincospif((float)tid * (1.0f / 128.0f), &s, &c);
        tw[tid] = make_float2(c, s);
    }
    int bo = blockIdx.x;

    const float4* zsrc = (const float4*)(g_Zo + (size_t)bo * QQ * M2);
    float4* zdst = (float4*)&sZ[0][0];
    for (int t = tid; t < QQ * M2 / 2; t += 256) zdst[t] = zsrc[t];
    __syncthreads();

    // ---- twiddle tables for phase 2 (wp = 0..63) ----
    for (int t = tid; t < M2 * 64; t += 256) {
        int k = t >> 6, wp = t & 63;
        float2 cs = tw[(k * wp) & 255];
        sCw[k][wp] = cs.x;
        sSw[k][wp] = cs.y;
    }

    // ---- phase 1 (unchanged, proven) ----
    {
        int h = tid & 127;
        int k0 = (tid >> 7) * 10;     // 0 or 10
        float ger[10], gei[10], gor[10], goi[10];
        #pragma unroll
        for (int j = 0; j < 10; ++j) { ger[j] = gei[j] = gor[j] = goi[j] = 0.f; }

        int step = (2 * h) & 255;
        int idx = (-20 * h) & 255;
        #pragma unroll 2
        for (int qq = 0; qq < 20; ++qq) {
            float2 cs = tw[idx];
            #pragma unroll
            for (int j = 0; j < 10; ++j) {
                float2 Z = sZ[2 * qq][k0 + j];
                ger[j] = fmaf(Z.x, cs.x, fmaf(-Z.y, cs.y, ger[j]));
                gei[j] = fmaf(Z.x, cs.y, fmaf( Z.y, cs.x, gei[j]));
            }
            idx = (idx + step) & 255;
        }
        idx = (-19 * h) & 255;
        #pragma unroll 2
        for (int qq = 0; qq < 20; ++qq) {
            float2 cs = tw[idx];
            #pragma unroll
            for (int j = 0; j < 10; ++j) {
                float2 Z = sZ[2 * qq + 1][k0 + j];
                gor[j] = fmaf(Z.x, cs.x, fmaf(-Z.y, cs.y, gor[j]));
                goi[j] = fmaf(Z.x, cs.y, fmaf( Z.y, cs.x, goi[j]));
            }
            idx = (idx + step) & 255;
        }
        #pragma unroll
        for (int j = 0; j < 10; ++j) {
            int k = k0 + j;
            sGx[k][h]       = ger[j] + gor[j];
            sGx[k][h + 128] = ger[j] - gor[j];
            if (k > 0) {
                sGy[k - 1][h]       = gei[j] + goi[j];
                sGy[k - 1][h + 128] = gei[j] - goi[j];
            }
        }
    }
    __syncthreads();

    // ---- phase 2: 4h x 2wp tiles, parity-folded over wp ----
    int wpg = tid & 31;       // wp0 = 2*wpg (0..62)
    int hgb = tid >> 5;       // 0..7
    int wp0 = wpg * 2;
    const float sc = 2.0f / 65536.0f;

    #pragma unroll 1
    for (int it = 0; it < 8; ++it) {
        int h0 = it * 32 + hgb * 4;
        float Ce[4][2], Co[4][2], Se[4][2], So[4][2];
        {
            float4 g0 = *(const float4*)&sGx[0][h0];
            float g0a[4] = {g0.x, g0.y, g0.z, g0.w};
            #pragma unroll
            for (int a = 0; a < 4; ++a)
                #pragma unroll
                for (int b = 0; b < 2; ++b) {
                    Ce[a][b] = 0.5f * g0a[a];
                    Co[a][b] = 0.f; Se[a][b] = 0.f; So[a][b] = 0.f;
                }
        }
        #pragma unroll
        for (int k = 1; k < M2; ++k) {
            float4 gx = *(const float4*)&sGx[k][h0];
            float4 gy = *(const float4*)&sGy[k - 1][h0];
            float2 cw = *(const float2*)&sCw[k][wp0];
            float2 sw = *(const float2*)&sSw[k][wp0];
            float gxa[4] = {gx.x, gx.y, gx.z, gx.w};
            float gya[4] = {gy.x, gy.y, gy.z, gy.w};
            float cwb[2] = {cw.x, cw.y};
            float swb[2] = {sw.x, sw.y};
            if (k & 1) {
                #pragma unroll
                for (int a = 0; a < 4; ++a)
                    #pragma unroll
                    for (int b = 0; b < 2; ++b) {
                        Co[a][b] = fmaf(gxa[a], cwb[b], Co[a][b]);
                        So[a][b] = fmaf(gya[a], swb[b], So[a][b]);
                    }
            } else {
                #pragma unroll
                for (int a = 0; a < 4; ++a)
                    #pragma unroll
                    for (int b = 0; b < 2; ++b) {
                        Ce[a][b] = fmaf(gxa[a], cwb[b], Ce[a][b]);
                        Se[a][b] = fmaf(gya[a], swb[b], Se[a][b]);
                    }
            }
        }

        size_t rowbase = ((size_t)bo * HH + h0) * WW;
        #pragma unroll
        for (int a = 0; a < 4; ++a) {
            float* orow = out + rowbase + (size_t)a * WW;
            float o1[2], o2[2], o3[2], o4[2];
            #pragma unroll
            for (int b = 0; b < 2; ++b) {
                float P = Ce[a][b], Q = Co[a][b], R = Se[a][b], T = So[a][b];
                o1[b] = (P + Q - R - T) * sc;   // out[wp]
                o2[b] = (P + Q + R + T) * sc;   // out[256-wp]
                o3[b] = (P - Q + R - T) * sc;   // out[128-wp]
                o4[b] = (P - Q - R + T) * sc;   // out[128+wp]
            }
            // forward pair (aligned float2)
            *(float2*)&orow[wp0] = make_float2(o1[0], o1[1]);
            if (wpg) {
                // mirrored columns (odd base -> scalars), 128+wp pair aligned
                orow[256 - wp0]     = o2[0];
                orow[255 - wp0]     = o2[1];
                orow[128 - wp0]     = o3[0];
                orow[127 - wp0]     = o3[1];
                *(float2*)&orow[128 + wp0] = make_float2(o4[0], o4[1]);
            } else {
                // wp0 = 0: wp=0 -> only out[0] (done above via o1[0]); wp=1 full set
                orow[255] = o2[1];
                orow[127] = o3[1];
                orow[129] = o4[1];
            }
        }
    }

    // ---- w = 64, 128, 192 columns (per-h epilogue) ----
    {
        int h = tid;
        float g0 = 0.5f * sGx[0][h];
        float accP = g0;      // even-k cos(pi k/2) sum + A
        float accS = 0.f;     // odd-k sin(pi k/2) sum
        float acc128 = g0;    // sum (-1)^k Gx
        #pragma unroll
        for (int k = 1; k < M2; ++k) {
            float gx = sGx[k][h];
            acc128 += (k & 1) ? -gx : gx;
            if (k & 1) {
                float gy = sGy[k - 1][h];
                accS += (((k - 1) >> 1) & 1) ? -gy : gy;   // sin(pi k/2) = (-1)^((k-1)/2)
            } else {
                accP += ((k >> 1) & 1) ? -gx : gx;          // cos(pi k/2) = (-1)^(k/2)
            }
        }
        float* orow = out + ((size_t)bo * HH + h) * WW;
        orow[64]  = (accP - accS) * sc;
        orow[192] = (accP + accS) * sc;
        orow[128] = acc128 * sc;
    }
}

extern "C" void kernel_launch(void* const* d_in, const int* in_sizes, int n_in,
                              void* d_out, int out_size) {
    const float* x   = (const float*)d_in[0];
    const float* w1r = (const float*)d_in[1];
    const float* w1i = (const float*)d_in[2];
    const float* w2r = (const float*)d_in[3];
    const float* w2i = (const float*)d_in[4];
    float* out = (float*)d_out;

    kA<<<(BB * CC * HH) / RA, 256>>>(x);       // 1024 blocks
    kB<<<BB * CC, 256>>>();                     // 1024 blocks
    kC<<<QQ * 5, 256>>>(w1r, w1i, w2r, w2i);    // 200 blocks
    kD<<<BB * CC, 256>>>(out);                  // 1024 blocks
}

// round 12
// speedup vs baseline: 1.2761x; 1.0120x over previous
#include <cuda_runtime.h>

// SpectralConv2d via truncated-mode DFTs, fp32 SIMT, register-tiled.

#define BB 16
#define CC 64
#define HH 256
#define WW 256
#define M1 20
#define M2 20
#define QQ 40   // q<20 -> ky=236+q (w2, m=q); q>=20 -> ky=q-20 (w1, m=q-20); freq f = q-20

__device__ float2 g_Y1[BB*CC*HH*M2];   // after W-DFT   [b,c,h,k2]
__device__ float2 g_Zq[BB*CC*QQ*M2];   // after H-DFT   [b,c,q,k2]
__device__ float2 g_Zo[BB*CC*QQ*M2];   // after mixing  [b,o,q,k2]

// ---------------------------------------------------------------------------
// Stage A: Y1[row,k] = sum_w x[row,w] e^{-2pi i k w/256}, k=0..19.
// Folded real input. Block: 256 rows, 256 threads; thread -> (4 rows, 5 k).
// ---------------------------------------------------------------------------
#define RA 256
#define WCH 32
__global__ void __launch_bounds__(256, 2) kA(const float* __restrict__ x) {
    __shared__ float2 tw[256];
    __shared__ float2 sf[RA][WCH + 1];   // 67.6KB: (u,v); chunk0 [..][0] = (x0,x128)
    __shared__ float2 twa[WCH][M2];      // 5KB
    int tid = threadIdx.x;
    {
        float s, c;
        sincospif((float)tid * (1.0f / 128.0f), &s, &c);
        tw[tid] = make_float2(c, s);
    }
    int row0 = blockIdx.x * RA;
    int rg = tid >> 2;             // 0..63 -> rows 4rg..4rg+3
    int k0 = (tid & 3) * 5;

    float ar[4][5], ai[4][5];
    #pragma unroll
    for (int u = 0; u < 4; ++u)
        #pragma unroll
        for (int j = 0; j < 5; ++j) { ar[u][j] = 0.0f; ai[u][j] = 0.0f; }
    float2 e[4];
    #pragma unroll
    for (int u = 0; u < 4; ++u) e[u] = make_float2(0.f, 0.f);

    for (int wc = 0; wc < 128; wc += WCH) {
        __syncthreads();
        for (int t = tid; t < RA * WCH; t += 256) {
            int r = t >> 5, wl = t & 31;
            int w = wc + wl;
            const float* xr = x + (size_t)(row0 + r) * WW;
            float a = xr[w];
            if (w == 0) {
                sf[r][wl] = make_float2(a, xr[128]);
            } else {
                float b = xr[256 - w];
                sf[r][wl] = make_float2(a + b, a - b);
            }
        }
        for (int t = tid; t < WCH * M2; t += 256) {
            int wl = t / M2, k = t - wl * M2;
            twa[wl][k] = tw[((wc + wl) * k) & 255];
        }
        __syncthreads();

        int wl0 = 0;
        if (wc == 0) {
            #pragma unroll
            for (int u = 0; u < 4; ++u) e[u] = sf[4 * rg + u][0];
            wl0 = 1;
        }

        #pragma unroll 2
        for (int wl = wl0; wl < WCH; ++wl) {
            float2 uv[4];
            #pragma unroll
            for (int u = 0; u < 4; ++u) uv[u] = sf[4 * rg + u][wl];
            #pragma unroll
            for (int j = 0; j < 5; ++j) {
                float2 cs = twa[wl][k0 + j];
                #pragma unroll
                for (int u = 0; u < 4; ++u) {
                    ar[u][j] = fmaf(uv[u].x, cs.x, ar[u][j]);
                    ai[u][j] = fmaf(uv[u].y, cs.y, ai[u][j]);
                }
            }
        }
    }

    #pragma unroll
    for (int u = 0; u < 4; ++u) {
        float2* yo = g_Y1 + (size_t)(row0 + 4 * rg + u) * M2;
        #pragma unroll
        for (int j = 0; j < 5; ++j) {
            int k = k0 + j;
            float re = ar[u][j] + e[u].x + ((k & 1) ? -e[u].y : e[u].y);
            yo[k] = make_float2(re, -ai[u][j]);
        }
    }
}

// ---------------------------------------------------------------------------
// Stage B: Zq[bc,q,k2] = sum_h Y1[bc,h,k2] e^{-2pi i f h/256}, f=q-20.
// h<->h+128 parity fold. Block per bc; thread -> (q, 4 k2), LDS.128 Y loads.
// ---------------------------------------------------------------------------
__global__ void __launch_bounds__(256) kB() {
    __shared__ float2 tw[256];
    __shared__ float2 sYp[128][M2];  // 20KB
    __shared__ float2 sYm[128][M2];  // 20KB
    int tid = threadIdx.x;
    {
        float s, c;
        sincospif((float)tid * (1.0f / 128.0f), &s, &c);
        tw[tid] = make_float2(c, s);
    }
    int bc = blockIdx.x;
    const float2* ysrc = g_Y1 + (size_t)bc * HH * M2;
    for (int t = tid; t < 128 * M2; t += 256) {
        int h = t / M2, k = t - h * M2;
        float2 a = ysrc[t];
        float2 b = ysrc[t + 128 * M2];
        sYp[h][k] = make_float2(a.x + b.x, a.y + b.y);
        sYm[h][k] = make_float2(a.x - b.x, a.y - b.y);
    }
    __syncthreads();

    if (tid < 200) {
        int q = tid / 5;
        int k0 = (tid % 5) * 4;
        int f = q - M1;
        const float2 (*Ys)[M2] = (f & 1) ? sYm : sYp;
        float ar[4] = {0, 0, 0, 0}, ai[4] = {0, 0, 0, 0};
        int idx = 0, step = f & 255;
        #pragma unroll 4
        for (int h = 0; h < 128; ++h) {
            float2 cs = tw[idx];
            float4 yab = *(const float4*)&Ys[h][k0];
            float4 ycd = *(const float4*)&Ys[h][k0 + 2];
            float yx[4] = {yab.x, yab.z, ycd.x, ycd.z};
            float yy[4] = {yab.y, yab.w, ycd.y, ycd.w};
            #pragma unroll
            for (int j = 0; j < 4; ++j) {
                ar[j] = fmaf(yx[j], cs.x, fmaf(yy[j], cs.y, ar[j]));
                ai[j] = fmaf(yy[j], cs.x, fmaf(-yx[j], cs.y, ai[j]));
            }
            idx = (idx + step) & 255;
        }
        float2* zo = g_Zq + (size_t)bc * QQ * M2 + q * M2 + k0;
        #pragma unroll
        for (int j = 0; j < 4; ++j) zo[j] = make_float2(ar[j], ai[j]);
    }
}

// ---------------------------------------------------------------------------
// Stage C: Zo[b,o,q,k2] = sum_i Zq[b,i,q,k2] * Wsel[i,o,m,k2]  (complex)
// Block per (q, k2-quad); weights loaded as float4 across 4 k2 (LDG.128);
// thread -> (o, 4 b, 4 k2).
// ---------------------------------------------------------------------------
__global__ void __launch_bounds__(256) kC(const float* __restrict__ w1r, const float* __restrict__ w1i,
                                          const float* __restrict__ w2r, const float* __restrict__ w2i) {
    __shared__ float2 sZ[BB][CC][4];  // 32KB
    int tid = threadIdx.x;
    int q = blockIdx.x / 5, k2b = (blockIdx.x % 5) * 4;

    for (int t = tid; t < BB * CC * 2; t += 256) {
        int pair = t & 1;
        int ci = t >> 1;                 // b*64 + i
        float4 v = *(const float4*)&g_Zq[(size_t)ci * (QQ * M2) + q * M2 + k2b + pair * 2];
        *(float4*)&sZ[ci >> 6][ci & 63][pair * 2] = v;
    }

    const float *wr, *wi;
    int m;
    if (q < M1) { wr = w2r; wi = w2i; m = q; }
    else        { wr = w1r; wi = w1i; m = q - M1; }
    __syncthreads();

    int o = tid & 63;
    int bq = tid >> 6;   // b = bq + 4j
    float ar[4][4], ai[4][4];
    #pragma unroll
    for (int j = 0; j < 4; ++j)
        #pragma unroll
        for (int kk = 0; kk < 4; ++kk) { ar[j][kk] = 0.f; ai[j][kk] = 0.f; }

    size_t wbase = (size_t)o * (M1 * M2) + m * M2 + k2b;
    #pragma unroll 2
    for (int i = 0; i < CC; ++i) {
        float4 wr4 = *(const float4*)&wr[wbase + (size_t)i * (CC * M1 * M2)];
        float4 wi4 = *(const float4*)&wi[wbase + (size_t)i * (CC * M1 * M2)];
        float wra[4] = {wr4.x, wr4.y, wr4.z, wr4.w};
        float wia[4] = {wi4.x, wi4.y, wi4.z, wi4.w};
        #pragma unroll
        for (int j = 0; j < 4; ++j) {
            float4 za = *(const float4*)&sZ[bq + 4 * j][i][0];
            float4 zb = *(const float4*)&sZ[bq + 4 * j][i][2];
            float zx[4] = {za.x, za.z, zb.x, zb.z};
            float zy[4] = {za.y, za.w, zb.y, zb.w};
            #pragma unroll
            for (int kk = 0; kk < 4; ++kk) {
                ar[j][kk] = fmaf(zx[kk], wra[kk], fmaf(-zy[kk], wia[kk], ar[j][kk]));
                ai[j][kk] = fmaf(zx[kk], wia[kk], fmaf( zy[kk], wra[kk], ai[j][kk]));
            }
        }
    }
    #pragma unroll
    for (int j = 0; j < 4; ++j) {
        int b = bq + 4 * j;
        float2* zo = g_Zo + (((size_t)(b * CC + o)) * QQ + q) * M2 + k2b;
        float4 v0 = make_float4(ar[j][0], ai[j][0], ar[j][1], ai[j][1]);
        float4 v1 = make_float4(ar[j][2], ai[j][2], ar[j][3], ai[j][3]);
        *(float4*)&zo[0] = v0;
        *(float4*)&zo[2] = v1;
    }
}

// ---------------------------------------------------------------------------
// Stage D (fused): block = one bo (grid 1024). NOW 2 CTAs/SM (regs 134 -> 128
// via launch bounds; only ~6 regs to shave, unlike R8's 223 -> 128 disaster).
// phase1: h<->h+128 fold by q-parity (proven R9 form).
// phase2: wp<->128-wp parity fold; one twiddle set -> 4 output columns.
// ---------------------------------------------------------------------------
__global__ void __launch_bounds__(256, 2) kD(float* __restrict__ out) {
    __shared__ float2 tw[256];          // 2KB
    __shared__ float2 sZ[QQ][M2];       // 6.25KB
    __shared__ float  sGx[M2][HH];      // 20KB
    __shared__ float  sGy[M2 - 1][HH];  // 19KB
    __shared__ float  sCw[M2][64];      // 5KB   cos(2pi k wp/256), wp<64
    __shared__ float  sSw[M2][64];      // 5KB   sin(2pi k wp/256), wp<64
    int tid = threadIdx.x;
    {
        float s, c;
        sincospif((float)tid * (1.0f / 128.0f), &s, &c);
        tw[tid] = make_float2(c, s);
    }
    int bo = blockIdx.x;

    const float4* zsrc = (const float4*)(g_Zo + (size_t)bo * QQ * M2);
    float4* zdst = (float4*)&sZ[0][0];
    for (int t = tid; t < QQ * M2 / 2; t += 256) zdst[t] = zsrc[t];
    __syncthreads();

    // ---- twiddle tables for phase 2 (wp = 0..63) ----
    for (int t = tid; t < M2 * 64; t += 256) {
        int k = t >> 6, wp = t & 63;
        float2 cs = tw[(k * wp) & 255];
        sCw[k][wp] = cs.x;
        sSw[k][wp] = cs.y;
    }

    // ---- phase 1 ----
    {
        int h = tid & 127;
        int k0 = (tid >> 7) * 10;     // 0 or 10
        float ger[10], gei[10], gor[10], goi[10];
        #pragma unroll
        for (int j = 0; j < 10; ++j) { ger[j] = gei[j] = gor[j] = goi[j] = 0.f; }

        int step = (2 * h) & 255;
        int idx = (-20 * h) & 255;
        #pragma unroll 2
        for (int qq = 0; qq < 20; ++qq) {
            float2 cs = tw[idx];
            #pragma unroll
            for (int j = 0; j < 10; ++j) {
                float2 Z = sZ[2 * qq][k0 + j];
                ger[j] = fmaf(Z.x, cs.x, fmaf(-Z.y, cs.y, ger[j]));
                gei[j] = fmaf(Z.x, cs.y, fmaf( Z.y, cs.x, gei[j]));
            }
            idx = (idx + step) & 255;
        }
        idx = (-19 * h) & 255;
        #pragma unroll 2
        for (int qq = 0; qq < 20; ++qq) {
            float2 cs = tw[idx];
            #pragma unroll
            for (int j = 0; j < 10; ++j) {
                float2 Z = sZ[2 * qq + 1][k0 + j];
                gor[j] = fmaf(Z.x, cs.x, fmaf(-Z.y, cs.y, gor[j]));
                goi[j] = fmaf(Z.x, cs.y, fmaf( Z.y, cs.x, goi[j]));
            }
            idx = (idx + step) & 255;
        }
        #pragma unroll
        for (int j = 0; j < 10; ++j) {
            int k = k0 + j;
            sGx[k][h]       = ger[j] + gor[j];
            sGx[k][h + 128] = ger[j] - gor[j];
            if (k > 0) {
                sGy[k - 1][h]       = gei[j] + goi[j];
                sGy[k - 1][h + 128] = gei[j] - goi[j];
            }
        }
    }
    __syncthreads();

    // ---- phase 2: 4h x 2wp tiles, parity-folded over wp ----
    int wpg = tid & 31;       // wp0 = 2*wpg (0..62)
    int hgb = tid >> 5;       // 0..7
    int wp0 = wpg * 2;
    const float sc = 2.0f / 65536.0f;

    #pragma unroll 1
    for (int it = 0; it < 8; ++it) {
        int h0 = it * 32 + hgb * 4;
        float Ce[4][2], Co[4][2], Se[4][2], So[4][2];
        {
            float4 g0 = *(const float4*)&sGx[0][h0];
            float g0a[4] = {g0.x, g0.y, g0.z, g0.w};
            #pragma unroll
            for (int a = 0; a < 4; ++a)
                #pragma unroll
                for (int b = 0; b < 2; ++b) {
                    Ce[a][b] = 0.5f * g0a[a];
                    Co[a][b] = 0.f; Se[a][b] = 0.f; So[a][b] = 0.f;
                }
        }
        #pragma unroll
        for (int k = 1; k < M2; ++k) {
            float4 gx = *(const float4*)&sGx[k][h0];
            float4 gy = *(const float4*)&sGy[k - 1][h0];
            float2 cw = *(const float2*)&sCw[k][wp0];
            float2 sw = *(const float2*)&sSw[k][wp0];
            float gxa[4] = {gx.x, gx.y, gx.z, gx.w};
            float gya[4] = {gy.x, gy.y, gy.z, gy.w};
            float cwb[2] = {cw.x, cw.y};
            float swb[2] = {sw.x, sw.y};
            if (k & 1) {
                #pragma unroll
                for (int a = 0; a < 4; ++a)
                    #pragma unroll
                    for (int b = 0; b < 2; ++b) {
                        Co[a][b] = fmaf(gxa[a], cwb[b], Co[a][b]);
                        So[a][b] = fmaf(gya[a], swb[b], So[a][b]);
                    }
            } else {
                #pragma unroll
                for (int a = 0; a < 4; ++a)
                    #pragma unroll
                    for (int b = 0; b < 2; ++b) {
                        Ce[a][b] = fmaf(gxa[a], cwb[b], Ce[a][b]);
                        Se[a][b] = fmaf(gya[a], swb[b], Se[a][b]);
                    }
            }
        }

        size_t rowbase = ((size_t)bo * HH + h0) * WW;
        #pragma unroll
        for (int a = 0; a < 4; ++a) {
            float* orow = out + rowbase + (size_t)a * WW;
            float o1[2], o2[2], o3[2], o4[2];
            #pragma unroll
            for (int b = 0; b < 2; ++b) {
                float P = Ce[a][b], Q = Co[a][b], R = Se[a][b], T = So[a][b];
                o1[b] = (P + Q - R - T) * sc;   // out[wp]
                o2[b] = (P + Q + R + T) * sc;   // out[256-wp]
                o3[b] = (P - Q + R - T) * sc;   // out[128-wp]
                o4[b] = (P - Q - R + T) * sc;   // out[128+wp]
            }
            *(float2*)&orow[wp0] = make_float2(o1[0], o1[1]);
            if (wpg) {
                orow[256 - wp0]     = o2[0];
                orow[255 - wp0]     = o2[1];
                orow[128 - wp0]     = o3[0];
                orow[127 - wp0]     = o3[1];
                *(float2*)&orow[128 + wp0] = make_float2(o4[0], o4[1]);
            } else {
                orow[255] = o2[1];
                orow[127] = o3[1];
                orow[129] = o4[1];
            }
        }
    }

    // ---- w = 64, 128, 192 columns (per-h epilogue) ----
    {
        int h = tid;
        float g0 = 0.5f * sGx[0][h];
        float accP = g0;
        float accS = 0.f;
        float acc128 = g0;
        #pragma unroll
        for (int k = 1; k < M2; ++k) {
            float gx = sGx[k][h];
            acc128 += (k & 1) ? -gx : gx;
            if (k & 1) {
                float gy = sGy[k - 1][h];
                accS += (((k - 1) >> 1) & 1) ? -gy : gy;
            } else {
                accP += ((k >> 1) & 1) ? -gx : gx;
            }
        }
        float* orow = out + ((size_t)bo * HH + h) * WW;
        orow[64]  = (accP - accS) * sc;
        orow[192] = (accP + accS) * sc;
        orow[128] = acc128 * sc;
    }
}

extern "C" void kernel_launch(void* const* d_in, const int* in_sizes, int n_in,
                              void* d_out, int out_size) {
    const float* x   = (const float*)d_in[0];
    const float* w1r = (const float*)d_in[1];
    const float* w1i = (const float*)d_in[2];
    const float* w2r = (const float*)d_in[3];
    const float* w2i = (const float*)d_in[4];
    float* out = (float*)d_out;

    kA<<<(BB * CC * HH) / RA, 256>>>(x);       // 1024 blocks
    kB<<<BB * CC, 256>>>();                     // 1024 blocks
    kC<<<QQ * 5, 256>>>(w1r, w1i, w2r, w2i);    // 200 blocks
    kD<<<BB * CC, 256>>>(out);                  // 1024 blocks
}

// round 13
// speedup vs baseline: 1.3754x; 1.0779x over previous
#include <cuda_runtime.h>

// SpectralConv2d via truncated-mode DFTs, fp32 SIMT, register-tiled.
// Round 13: kA+kB fused (g_Y1 round-trip eliminated); kC/kD banked from R12.

#define BB 16
#define CC 64
#define HH 256
#define WW 256
#define M1 20
#define M2 20
#define QQ 40   // q<20 -> ky=236+q (w2, m=q); q>=20 -> ky=q-20 (w1, m=q-20); freq f = q-20

__device__ float2 g_Zq[BB*CC*QQ*M2];   // after H-DFT   [b,c,q,k2]
__device__ float2 g_Zo[BB*CC*QQ*M2];   // after mixing  [b,o,q,k2]

// ---------------------------------------------------------------------------
// Stage AB (fused): block = one (b,c) slice (grid 1024), 256 threads.
// part 1 (W-DFT): Y[h,k] = sum_w x[h,w] e^{-2pi i k w/256}, k=0..19, folded
//   real input (u=x[w]+x[256-w], v=x[w]-x[256-w], + x0/x128 edge).
//   thread -> (4 rows, 5 k); Y lands in smem sY[256][20].
// fold: in place, sY[h] <- Y[h]+Y[h+128] (plane p), sY[h+128] <- Y[h]-Y[h+128].
// part 2 (H-DFT): Zq[q,k2] = sum_{h<128} plane(f&1)[h][k2] e^{-2pi i f h/256},
//   f = q-20; thread -> (q, 4 k2); writes g_Zq.
// ---------------------------------------------------------------------------
#define WCH 16
__global__ void __launch_bounds__(256, 2) kAB(const float* __restrict__ x) {
    __shared__ float2 tw[256];            // 2KB
    __shared__ float2 sf[HH][WCH + 1];    // 34KB: (u,v); chunk0 [..][0] = (x0,x128)
    __shared__ float2 twa[WCH][M2];       // 2.5KB
    __shared__ float2 sY[HH][M2];         // 40KB
    int tid = threadIdx.x;
    {
        float s, c;
        sincospif((float)tid * (1.0f / 128.0f), &s, &c);
        tw[tid] = make_float2(c, s);
    }
    int bc = blockIdx.x;
    const float* xb = x + (size_t)bc * HH * WW;
    int rg = tid >> 2;             // 0..63 -> rows 4rg..4rg+3
    int k0a = (tid & 3) * 5;

    float ar[4][5], ai[4][5];
    #pragma unroll
    for (int u = 0; u < 4; ++u)
        #pragma unroll
        for (int j = 0; j < 5; ++j) { ar[u][j] = 0.0f; ai[u][j] = 0.0f; }
    float2 e[4];
    #pragma unroll
    for (int u = 0; u < 4; ++u) e[u] = make_float2(0.f, 0.f);

    for (int wc = 0; wc < 128; wc += WCH) {
        __syncthreads();
        for (int t = tid; t < HH * WCH; t += 256) {
            int r = t >> 4, wl = t & 15;
            int w = wc + wl;
            const float* xr = xb + (size_t)r * WW;
            float a = xr[w];
            if (w == 0) {
                sf[r][0] = make_float2(a, xr[128]);
            } else {
                float b = xr[256 - w];
                sf[r][wl] = make_float2(a + b, a - b);
            }
        }
        for (int t = tid; t < WCH * M2; t += 256) {
            int wl = t / M2, k = t - wl * M2;
            twa[wl][k] = tw[((wc + wl) * k) & 255];
        }
        __syncthreads();

        int wl0 = 0;
        if (wc == 0) {
            #pragma unroll
            for (int u = 0; u < 4; ++u) e[u] = sf[4 * rg + u][0];
            wl0 = 1;
        }

        #pragma unroll 2
        for (int wl = wl0; wl < WCH; ++wl) {
            float2 uv[4];
            #pragma unroll
            for (int u = 0; u < 4; ++u) uv[u] = sf[4 * rg + u][wl];
            #pragma unroll
            for (int j = 0; j < 5; ++j) {
                float2 cs = twa[wl][k0a + j];
                #pragma unroll
                for (int u = 0; u < 4; ++u) {
                    ar[u][j] = fmaf(uv[u].x, cs.x, ar[u][j]);
                    ai[u][j] = fmaf(uv[u].y, cs.y, ai[u][j]);
                }
            }
        }
    }

    // Y -> smem
    #pragma unroll
    for (int u = 0; u < 4; ++u) {
        #pragma unroll
        for (int j = 0; j < 5; ++j) {
            int k = k0a + j;
            float re = ar[u][j] + e[u].x + ((k & 1) ? -e[u].y : e[u].y);
            sY[4 * rg + u][k] = make_float2(re, -ai[u][j]);
        }
    }
    __syncthreads();

    // in-place parity fold: sY[h] = Y[h]+Y[h+128], sY[h+128] = Y[h]-Y[h+128]
    for (int t = tid; t < 128 * M2; t += 256) {
        int h = t / M2, k = t - h * M2;
        float2 a = sY[h][k];
        float2 b = sY[h + 128][k];
        sY[h][k]       = make_float2(a.x + b.x, a.y + b.y);
        sY[h + 128][k] = make_float2(a.x - b.x, a.y - b.y);
    }
    __syncthreads();

    // part 2: H-DFT (kB loop)
    if (tid < 200) {
        int q = tid / 5;
        int k0 = (tid % 5) * 4;
        int f = q - M1;
        const float2 (*Ys)[M2] = (f & 1) ? (const float2(*)[M2])&sY[128] : (const float2(*)[M2])&sY[0];
        float br[4] = {0, 0, 0, 0}, bi[4] = {0, 0, 0, 0};
        int idx = 0, step = f & 255;
        #pragma unroll 4
        for (int h = 0; h < 128; ++h) {
            float2 cs = tw[idx];
            float4 yab = *(const float4*)&Ys[h][k0];
            float4 ycd = *(const float4*)&Ys[h][k0 + 2];
            float yx[4] = {yab.x, yab.z, ycd.x, ycd.z};
            float yy[4] = {yab.y, yab.w, ycd.y, ycd.w};
            #pragma unroll
            for (int j = 0; j < 4; ++j) {
                br[j] = fmaf(yx[j], cs.x, fmaf(yy[j], cs.y, br[j]));
                bi[j] = fmaf(yy[j], cs.x, fmaf(-yx[j], cs.y, bi[j]));
            }
            idx = (idx + step) & 255;
        }
        float2* zo = g_Zq + (size_t)bc * QQ * M2 + q * M2 + k0;
        #pragma unroll
        for (int j = 0; j < 4; ++j) zo[j] = make_float2(br[j], bi[j]);
    }
}

// ---------------------------------------------------------------------------
// Stage C: Zo[b,o,q,k2] = sum_i Zq[b,i,q,k2] * Wsel[i,o,m,k2]  (complex)
// Block per (q, k2-quad); weights loaded as float4 across 4 k2 (LDG.128);
// thread -> (o, 4 b, 4 k2).
// ---------------------------------------------------------------------------
__global__ void __launch_bounds__(256) kC(const float* __restrict__ w1r, const float* __restrict__ w1i,
                                          const float* __restrict__ w2r, const float* __restrict__ w2i) {
    __shared__ float2 sZ[BB][CC][4];  // 32KB
    int tid = threadIdx.x;
    int q = blockIdx.x / 5, k2b = (blockIdx.x % 5) * 4;

    for (int t = tid; t < BB * CC * 2; t += 256) {
        int pair = t & 1;
        int ci = t >> 1;                 // b*64 + i
        float4 v = *(const float4*)&g_Zq[(size_t)ci * (QQ * M2) + q * M2 + k2b + pair * 2];
        *(float4*)&sZ[ci >> 6][ci & 63][pair * 2] = v;
    }

    const float *wr, *wi;
    int m;
    if (q < M1) { wr = w2r; wi = w2i; m = q; }
    else        { wr = w1r; wi = w1i; m = q - M1; }
    __syncthreads();

    int o = tid & 63;
    int bq = tid >> 6;   // b = bq + 4j
    float ar[4][4], ai[4][4];
    #pragma unroll
    for (int j = 0; j < 4; ++j)
        #pragma unroll
        for (int kk = 0; kk < 4; ++kk) { ar[j][kk] = 0.f; ai[j][kk] = 0.f; }

    size_t wbase = (size_t)o * (M1 * M2) + m * M2 + k2b;
    #pragma unroll 2
    for (int i = 0; i < CC; ++i) {
        float4 wr4 = *(const float4*)&wr[wbase + (size_t)i * (CC * M1 * M2)];
        float4 wi4 = *(const float4*)&wi[wbase + (size_t)i * (CC * M1 * M2)];
        float wra[4] = {wr4.x, wr4.y, wr4.z, wr4.w};
        float wia[4] = {wi4.x, wi4.y, wi4.z, wi4.w};
        #pragma unroll
        for (int j = 0; j < 4; ++j) {
            float4 za = *(const float4*)&sZ[bq + 4 * j][i][0];
            float4 zb = *(const float4*)&sZ[bq + 4 * j][i][2];
            float zx[4] = {za.x, za.z, zb.x, zb.z};
            float zy[4] = {za.y, za.w, zb.y, zb.w};
            #pragma unroll
            for (int kk = 0; kk < 4; ++kk) {
                ar[j][kk] = fmaf(zx[kk], wra[kk], fmaf(-zy[kk], wia[kk], ar[j][kk]));
                ai[j][kk] = fmaf(zx[kk], wia[kk], fmaf( zy[kk], wra[kk], ai[j][kk]));
            }
        }
    }
    #pragma unroll
    for (int j = 0; j < 4; ++j) {
        int b = bq + 4 * j;
        float2* zo = g_Zo + (((size_t)(b * CC + o)) * QQ + q) * M2 + k2b;
        float4 v0 = make_float4(ar[j][0], ai[j][0], ar[j][1], ai[j][1]);
        float4 v1 = make_float4(ar[j][2], ai[j][2], ar[j][3], ai[j][3]);
        *(float4*)&zo[0] = v0;
        *(float4*)&zo[2] = v1;
    }
}

// ---------------------------------------------------------------------------
// Stage D (fused irfft2): block = one bo (grid 1024), 2 CTAs/SM (regs=128).
// phase1: h<->h+128 fold by q-parity. phase2: wp<->128-wp parity fold; one
// twiddle set -> 4 output columns. (Banked R12 form.)
// ---------------------------------------------------------------------------
__global__ void __launch_bounds__(256, 2) kD(float* __restrict__ out) {
    __shared__ float2 tw[256];          // 2KB
    __shared__ float2 sZ[QQ][M2];       // 6.25KB
    __shared__ float  sGx[M2][HH];      // 20KB
    __shared__ float  sGy[M2 - 1][HH];  // 19KB
    __shared__ float  sCw[M2][64];      // 5KB   cos(2pi k wp/256), wp<64
    __shared__ float  sSw[M2][64];      // 5KB   sin(2pi k wp/256), wp<64
    int tid = threadIdx.x;
    {
        float s, c;
        sincospif((float)tid * (1.0f / 128.0f), &s, &c);
        tw[tid] = make_float2(c, s);
    }
    int bo = blockIdx.x;

    const float4* zsrc = (const float4*)(g_Zo + (size_t)bo * QQ * M2);
    float4* zdst = (float4*)&sZ[0][0];
    for (int t = tid; t < QQ * M2 / 2; t += 256) zdst[t] = zsrc[t];
    __syncthreads();

    for (int t = tid; t < M2 * 64; t += 256) {
        int k = t >> 6, wp = t & 63;
        float2 cs = tw[(k * wp) & 255];
        sCw[k][wp] = cs.x;
        sSw[k][wp] = cs.y;
    }

    // ---- phase 1 ----
    {
        int h = tid & 127;
        int k0 = (tid >> 7) * 10;     // 0 or 10
        float ger[10], gei[10], gor[10], goi[10];
        #pragma unroll
        for (int j = 0; j < 10; ++j) { ger[j] = gei[j] = gor[j] = goi[j] = 0.f; }

        int step = (2 * h) & 255;
        int idx = (-20 * h) & 255;
        #pragma unroll 2
        for (int qq = 0; qq < 20; ++qq) {
            float2 cs = tw[idx];
            #pragma unroll
            for (int j = 0; j < 10; ++j) {
                float2 Z = sZ[2 * qq][k0 + j];
                ger[j] = fmaf(Z.x, cs.x, fmaf(-Z.y, cs.y, ger[j]));
                gei[j] = fmaf(Z.x, cs.y, fmaf( Z.y, cs.x, gei[j]));
            }
            idx = (idx + step) & 255;
        }
        idx = (-19 * h) & 255;
        #pragma unroll 2
        for (int qq = 0; qq < 20; ++qq) {
            float2 cs = tw[idx];
            #pragma unroll
            for (int j = 0; j < 10; ++j) {
                float2 Z = sZ[2 * qq + 1][k0 + j];
                gor[j] = fmaf(Z.x, cs.x, fmaf(-Z.y, cs.y, gor[j]));
                goi[j] = fmaf(Z.x, cs.y, fmaf( Z.y, cs.x, goi[j]));
            }
            idx = (idx + step) & 255;
        }
        #pragma unroll
        for (int j = 0; j < 10; ++j) {
            int k = k0 + j;
            sGx[k][h]       = ger[j] + gor[j];
            sGx[k][h + 128] = ger[j] - gor[j];
            if (k > 0) {
                sGy[k - 1][h]       = gei[j] + goi[j];
                sGy[k - 1][h + 128] = gei[j] - goi[j];
            }
        }
    }
    __syncthreads();

    // ---- phase 2: 4h x 2wp tiles, parity-folded over wp ----
    int wpg = tid & 31;       // wp0 = 2*wpg (0..62)
    int hgb = tid >> 5;       // 0..7
    int wp0 = wpg * 2;
    const float sc = 2.0f / 65536.0f;

    #pragma unroll 1
    for (int it = 0; it < 8; ++it) {
        int h0 = it * 32 + hgb * 4;
        float Ce[4][2], Co[4][2], Se[4][2], So[4][2];
        {
            float4 g0 = *(const float4*)&sGx[0][h0];
            float g0a[4] = {g0.x, g0.y, g0.z, g0.w};
            #pragma unroll
            for (int a = 0; a < 4; ++a)
                #pragma unroll
                for (int b = 0; b < 2; ++b) {
                    Ce[a][b] = 0.5f * g0a[a];
                    Co[a][b] = 0.f; Se[a][b] = 0.f; So[a][b] = 0.f;
                }
        }
        #pragma unroll
        for (int k = 1; k < M2; ++k) {
            float4 gx = *(const float4*)&sGx[k][h0];
            float4 gy = *(const float4*)&sGy[k - 1][h0];
            float2 cw = *(const float2*)&sCw[k][wp0];
            float2 sw = *(const float2*)&sSw[k][wp0];
            float gxa[4] = {gx.x, gx.y, gx.z, gx.w};
            float gya[4] = {gy.x, gy.y, gy.z, gy.w};
            float cwb[2] = {cw.x, cw.y};
            float swb[2] = {sw.x, sw.y};
            if (k & 1) {
                #pragma unroll
                for (int a = 0; a < 4; ++a)
                    #pragma unroll
                    for (int b = 0; b < 2; ++b) {
                        Co[a][b] = fmaf(gxa[a], cwb[b], Co[a][b]);
                        So[a][b] = fmaf(gya[a], swb[b], So[a][b]);
                    }
            } else {
                #pragma unroll
                for (int a = 0; a < 4; ++a)
                    #pragma unroll
                    for (int b = 0; b < 2; ++b) {
                        Ce[a][b] = fmaf(gxa[a], cwb[b], Ce[a][b]);
                        Se[a][b] = fmaf(gya[a], swb[b], Se[a][b]);
                    }
            }
        }

        size_t rowbase = ((size_t)bo * HH + h0) * WW;
        #pragma unroll
        for (int a = 0; a < 4; ++a) {
            float* orow = out + rowbase + (size_t)a * WW;
            float o1[2], o2[2], o3[2], o4[2];
            #pragma unroll
            for (int b = 0; b < 2; ++b) {
                float P = Ce[a][b], Q = Co[a][b], R = Se[a][b], T = So[a][b];
                o1[b] = (P + Q - R - T) * sc;   // out[wp]
                o2[b] = (P + Q + R + T) * sc;   // out[256-wp]
                o3[b] = (P - Q + R - T) * sc;   // out[128-wp]
                o4[b] = (P - Q - R + T) * sc;   // out[128+wp]
            }
            *(float2*)&orow[wp0] = make_float2(o1[0], o1[1]);
            if (wpg) {
                orow[256 - wp0]     = o2[0];
                orow[255 - wp0]     = o2[1];
                orow[128 - wp0]     = o3[0];
                orow[127 - wp0]     = o3[1];
                *(float2*)&orow[128 + wp0] = make_float2(o4[0], o4[1]);
            } else {
                orow[255] = o2[1];
                orow[127] = o3[1];
                orow[129] = o4[1];
            }
        }
    }

    // ---- w = 64, 128, 192 columns (per-h epilogue) ----
    {
        int h = tid;
        float g0 = 0.5f * sGx[0][h];
        float accP = g0;
        float accS = 0.f;
        float acc128 = g0;
        #pragma unroll
        for (int k = 1; k < M2; ++k) {
            float gx = sGx[k][h];
            acc128 += (k & 1) ? -gx : gx;
            if (k & 1) {
                float gy = sGy[k - 1][h];
                accS += (((k - 1) >> 1) & 1) ? -gy : gy;
            } else {
                accP += ((k >> 1) & 1) ? -gx : gx;
            }
        }
        float* orow = out + ((size_t)bo * HH + h) * WW;
        orow[64]  = (accP - accS) * sc;
        orow[192] = (accP + accS) * sc;
        orow[128] = acc128 * sc;
    }
}

extern "C" void kernel_launch(void* const* d_in, const int* in_sizes, int n_in,
                              void* d_out, int out_size) {
    const float* x   = (const float*)d_in[0];
    const float* w1r = (const float*)d_in[1];
    const float* w1i = (const float*)d_in[2];
    const float* w2r = (const float*)d_in[3];
    const float* w2i = (const float*)d_in[4];
    float* out = (float*)d_out;

    kAB<<<BB * CC, 256>>>(x);                   // 1024 blocks (fused A+B)
    kC<<<QQ * 5, 256>>>(w1r, w1i, w2r, w2i);    // 200 blocks
    kD<<<BB * CC, 256>>>(out);                  // 1024 blocks
}